// round 5
// baseline (speedup 1.0000x reference)
#include <cuda_runtime.h>
#include <cuda_bf16.h>

// ---------------------------------------------------------------------------
// EventTokenizer, single persistent kernel with internal grid barriers.
// T=262144 frames, D_IN=512, K=64 contiguous segments partitioning [0,T).
// Phase A: feature sums (512MB stream) + scalar reductions
// Phase B: motion entropy (needs sum_e)
// Phase C: GEMM tokens + epilogue outputs
// Phase D: re-zero scratch for next graph replay
// ---------------------------------------------------------------------------

#define TFRAMES   262144
#define KSEG      64
#define DIN       512
#define DMODEL    256
#define TYPEEMB   32
#define ZDIM      552      // 512 + 8 + 32
#define EPSF      1e-6f
#define CONF_TH   0.3f

// Output layout (float32, concatenated in reference return order):
// tokens [64*256] | mask [64] | type [64] | conf [64] | s_k [64*8]
#define OUT_TOKENS 0
#define OUT_MASK   16384
#define OUT_TYPE   16448
#define OUT_CONF   16512
#define OUT_SK     16576

// ----- scratch (zero at module load; phase D re-zeros for next replay) -----
__device__ float    g_esum[KSEG * DIN];
__device__ float    g_sumE[KSEG];
__device__ int      g_maxE[KSEG];       // float bits (energy >= 0)
__device__ float    g_sumFC[KSEG];
__device__ float    g_sumSC[KSEG * 3];
__device__ float    g_ent[KSEG];        // sum p*log(p+eps)
__device__ unsigned g_barc = 0;         // barrier arrival counter
__device__ unsigned g_barg = 0;         // barrier generation (monotonic)

// grid-wide barrier: counter + generation. Counter is reset by the last
// arriver before the gen bump, so it is reusable; gen grows monotonically
// across syncs and replays (no reset needed).
__device__ __forceinline__ void gsync(unsigned nblocks) {
    __syncthreads();
    if (threadIdx.x == 0) {
        __threadfence();
        unsigned gen = *(volatile unsigned*)&g_barg;
        if (atomicAdd(&g_barc, 1u) == nblocks - 1u) {
            g_barc = 0;
            __threadfence();
            atomicAdd(&g_barg, 1u);
        } else {
            while (*(volatile unsigned*)&g_barg == gen) __nanosleep(128);
        }
        __threadfence();
    }
    __syncthreads();
}

// segment of frame f = smallest i with send[i] > f (binary search, 6 steps)
__device__ __forceinline__ int seg_of(const int* send, int f) {
    int lo = 0, hi = KSEG - 1;
    #pragma unroll
    for (int it = 0; it < 6; ++it) {
        int mid = (lo + hi) >> 1;
        if (send[mid] > f) hi = mid; else lo = mid + 1;
    }
    return lo;
}

__global__ void __launch_bounds__(256, 4)
k_all(const float4* __restrict__ feat,
      const float*  __restrict__ energy,
      const float*  __restrict__ fconf,
      const float*  __restrict__ sconf,
      const int*    __restrict__ segstart,
      const int*    __restrict__ segend,
      const int*    __restrict__ etype,
      const float*  __restrict__ emb,
      const float*  __restrict__ W,
      const float*  __restrict__ bias,
      const int*    __restrict__ fpsp,
      float*        __restrict__ out) {
    __shared__ int   send[KSEG];
    __shared__ float sinv[KSEG];
    __shared__ float z[ZDIM];

    const int tid = threadIdx.x;
    const unsigned G = gridDim.x;
    if (tid < KSEG) send[tid] = segend[tid];
    __syncthreads();

    // ================= Phase A: accumulate =================
    // items 0..511: feature chunks of 512 frames (two 256-frame halves,
    //   threads [0,128) own half 0, [128,256) half 1; thread col = tid&127
    //   owns float4 columns [4c,4c+4) of each frame).
    // items 512..575: scalar chunks of 4096 frames.
    for (int item = blockIdx.x; item < 576; item += G) {
        if (item < 512) {
            const int h   = tid >> 7;
            const int col = tid & 127;
            const int f0  = item * 512 + h * 256;
            const int f1  = f0 + 256;
            int cur = seg_of(send, f0);
            const float4* p = feat + (size_t)f0 * 128 + col;

            if (send[cur] >= f1) {
                // fast path: whole half-chunk in one segment
                float4 a0 = make_float4(0.f, 0.f, 0.f, 0.f);
                float4 a1 = make_float4(0.f, 0.f, 0.f, 0.f);
                #pragma unroll 4
                for (int i = 0; i < 256; i += 2) {
                    float4 v0 = __ldcs(p + (size_t)i * 128);
                    float4 v1 = __ldcs(p + (size_t)(i + 1) * 128);
                    a0.x += v0.x; a0.y += v0.y; a0.z += v0.z; a0.w += v0.w;
                    a1.x += v1.x; a1.y += v1.y; a1.z += v1.z; a1.w += v1.w;
                }
                a0.x += a1.x; a0.y += a1.y; a0.z += a1.z; a0.w += a1.w;
                float* dst = &g_esum[cur * DIN + col * 4];
                atomicAdd(dst + 0, a0.x); atomicAdd(dst + 1, a0.y);
                atomicAdd(dst + 2, a0.z); atomicAdd(dst + 3, a0.w);
            } else {
                float4 acc = make_float4(0.f, 0.f, 0.f, 0.f);
                for (int f = f0; f < f1; ++f, p += 128) {
                    if (f >= send[cur]) {
                        float* dst = &g_esum[cur * DIN + col * 4];
                        atomicAdd(dst + 0, acc.x); atomicAdd(dst + 1, acc.y);
                        atomicAdd(dst + 2, acc.z); atomicAdd(dst + 3, acc.w);
                        acc = make_float4(0.f, 0.f, 0.f, 0.f);
                        while (send[cur] <= f) cur++;
                    }
                    float4 v = __ldcs(p);
                    acc.x += v.x; acc.y += v.y; acc.z += v.z; acc.w += v.w;
                }
                float* dst = &g_esum[cur * DIN + col * 4];
                atomicAdd(dst + 0, acc.x); atomicAdd(dst + 1, acc.y);
                atomicAdd(dst + 2, acc.z); atomicAdd(dst + 3, acc.w);
            }
        } else {
            const int base = (item - 512) * 4096 + tid;   // 16 iters stride 256
            int cur = seg_of(send, base);
            float sE = 0.f, mx = 0.f, aF = 0.f, s0 = 0.f, s1 = 0.f, s2 = 0.f;
            #pragma unroll 8
            for (int i = 0; i < 16; ++i) {
                int f = base + i * 256;
                if (f >= send[cur]) {
                    atomicAdd(&g_sumE[cur], sE);
                    atomicMax(&g_maxE[cur], __float_as_int(mx));
                    atomicAdd(&g_sumFC[cur], aF);
                    atomicAdd(&g_sumSC[cur * 3 + 0], s0);
                    atomicAdd(&g_sumSC[cur * 3 + 1], s1);
                    atomicAdd(&g_sumSC[cur * 3 + 2], s2);
                    sE = mx = aF = s0 = s1 = s2 = 0.f;
                    while (send[cur] <= f) cur++;
                }
                float e = energy[f];
                sE += e; mx = fmaxf(mx, e);
                aF += fconf[f];
                s0 += sconf[3 * f + 0]; s1 += sconf[3 * f + 1]; s2 += sconf[3 * f + 2];
            }
            atomicAdd(&g_sumE[cur], sE);
            atomicMax(&g_maxE[cur], __float_as_int(mx));
            atomicAdd(&g_sumFC[cur], aF);
            atomicAdd(&g_sumSC[cur * 3 + 0], s0);
            atomicAdd(&g_sumSC[cur * 3 + 1], s1);
            atomicAdd(&g_sumSC[cur * 3 + 2], s2);
        }
    }

    gsync(G);

    // ================= Phase B: entropy =================
    if (tid < KSEG) sinv[tid] = 1.f / (g_sumE[tid] + EPSF);
    __syncthreads();

    for (int f = blockIdx.x * 256 + tid; f < TFRAMES; f += G * 256) {
        int cur = seg_of(send, f);
        float p = energy[f] * sinv[cur];
        float v = p * __logf(p + EPSF);
        // warp-aggregate when the whole warp is in one segment (common case)
        int first = __shfl_sync(~0u, cur, 0);
        if (__all_sync(~0u, cur == first)) {
            #pragma unroll
            for (int o = 16; o; o >>= 1) v += __shfl_xor_sync(~0u, v, o);
            if ((tid & 31) == 0) atomicAdd(&g_ent[cur], v);
        } else {
            atomicAdd(&g_ent[cur], v);
        }
    }

    gsync(G);

    // ================= Phase C: GEMM + epilogue =================
    // items 0..255: gemm tile (k = item>>2, 64 rows). item 256: epilogue.
    // fps may arrive as int32 or float32: sniff the bit pattern.
    const int  iv  = fpsp[0];
    const float fps = (iv >= 1 && iv <= 1000000) ? (float)iv : __int_as_float(iv);

    for (int item = blockIdx.x; item < 257; item += G) {
        if (item < 256) {
            const int k  = item >> 2;
            const int s  = segstart[k];
            const int e  = segend[k];
            const float len = (float)(e - s);
            const float inv = 1.f / len;
            const int  ty   = etype[k];

            // s_k recomputed inline (cheap) to avoid an extra sync
            float sk[8];
            sk[0] = log1pf(len / fps);
            sk[1] = log1pf((float)s / fps);
            sk[2] = log1pf(g_sumE[k] * inv);
            sk[3] = log1pf(__int_as_float(g_maxE[k]));
            sk[4] = log1pf(-g_ent[k]);
            sk[5] = log1pf(g_sumSC[k * 3 + 0] * inv);
            sk[6] = log1pf(g_sumSC[k * 3 + 1] * inv);
            sk[7] = log1pf(g_sumSC[k * 3 + 2] * inv);

            for (int i = tid; i < ZDIM; i += 256) {
                float v;
                if (i < DIN)            v = g_esum[k * DIN + i] * inv;
                else if (i < DIN + 8)   v = sk[i - DIN];
                else                    v = emb[ty * TYPEEMB + (i - DIN - 8)];
                z[i] = v;
            }
            __syncthreads();

            const int w     = tid >> 5;
            const int lane  = tid & 31;
            const int mbase = (item & 3) * 64 + w * 8;
            #pragma unroll
            for (int r = 0; r < 8; ++r) {
                const int m = mbase + r;
                const float* Wr = W + (size_t)m * ZDIM;
                float acc = 0.f;
                for (int j = lane; j < ZDIM; j += 32) acc += z[j] * Wr[j];
                #pragma unroll
                for (int o = 16; o; o >>= 1) acc += __shfl_xor_sync(~0u, acc, o);
                if (lane == 0) out[OUT_TOKENS + k * DMODEL + m] = acc + bias[m];
            }
            __syncthreads();
        } else if (tid < KSEG) {
            const int k = tid;
            const int s = segstart[k];
            const int e = segend[k];
            const float len = (float)(e - s);
            const float inv = 1.f / len;
            float sk[8];
            sk[0] = log1pf(len / fps);
            sk[1] = log1pf((float)s / fps);
            sk[2] = log1pf(g_sumE[k] * inv);
            sk[3] = log1pf(__int_as_float(g_maxE[k]));
            sk[4] = log1pf(-g_ent[k]);
            sk[5] = log1pf(g_sumSC[k * 3 + 0] * inv);
            sk[6] = log1pf(g_sumSC[k * 3 + 1] * inv);
            sk[7] = log1pf(g_sumSC[k * 3 + 2] * inv);
            #pragma unroll
            for (int i = 0; i < 8; ++i) out[OUT_SK + k * 8 + i] = sk[i];
            float conf = g_sumFC[k] * inv;
            out[OUT_MASK + k] = (conf >= CONF_TH) ? 1.f : 0.f;
            out[OUT_TYPE + k] = (float)etype[k];
            out[OUT_CONF + k] = conf;
        }
    }

    gsync(G);

    // ================= Phase D: re-zero scratch for next replay =================
    for (int i = blockIdx.x * 256 + tid; i < KSEG * DIN; i += G * 256) g_esum[i] = 0.f;
    if (blockIdx.x == 0 && tid < KSEG) {
        g_sumE[tid] = 0.f; g_maxE[tid] = 0; g_sumFC[tid] = 0.f; g_ent[tid] = 0.f;
        g_sumSC[tid * 3 + 0] = 0.f; g_sumSC[tid * 3 + 1] = 0.f; g_sumSC[tid * 3 + 2] = 0.f;
    }
}

// ---------------------------------------------------------------------------
extern "C" void kernel_launch(void* const* d_in, const int* in_sizes, int n_in,
                              void* d_out, int out_size) {
    const float* features  = (const float*)d_in[0];   // [T, 512]
    const float* energy    = (const float*)d_in[1];   // [T]
    const float* fconf     = (const float*)d_in[2];   // [T]
    const float* sconf     = (const float*)d_in[3];   // [T, 3]
    const int*   seg_start = (const int*)  d_in[4];   // [64]
    const int*   seg_end   = (const int*)  d_in[5];   // [64]
    const int*   etype     = (const int*)  d_in[6];   // [64]
    const float* emb       = (const float*)d_in[7];   // [16, 32]
    const float* W         = (const float*)d_in[8];   // [256, 552]
    const float* bias      = (const float*)d_in[9];   // [256]
    const int*   fps       = (const int*)  d_in[10];  // scalar
    float* out = (float*)d_out;

    // persistent grid: exactly the co-resident capacity (barrier safety)
    int sms = 0, occ = 0;
    cudaDeviceGetAttribute(&sms, cudaDevAttrMultiProcessorCount, 0);
    cudaOccupancyMaxActiveBlocksPerMultiprocessor(&occ, k_all, 256, 0);
    if (occ < 1) occ = 1;
    int grid = sms * occ;

    k_all<<<grid, 256>>>((const float4*)features, energy, fconf, sconf,
                         seg_start, seg_end, etype, emb, W, bias, fps, out);
}

// round 6
// speedup vs baseline: 1.3340x; 1.3340x over previous
#include <cuda_runtime.h>
#include <cuda_bf16.h>

// ---------------------------------------------------------------------------
// EventTokenizer, single persistent kernel with internal grid barriers.
// T=262144 frames, D_IN=512, K=64 contiguous segments partitioning [0,T).
// Phase A: feature sums (512MB stream, explicit MLP-8 batching) + scalars
// Phase B: motion entropy (needs sum_e)
// Phase C: GEMM tokens + epilogue outputs
// Phase D: re-zero scratch for next graph replay
// ---------------------------------------------------------------------------

#define TFRAMES   262144
#define KSEG      64
#define DIN       512
#define DMODEL    256
#define TYPEEMB   32
#define ZDIM      552      // 512 + 8 + 32
#define EPSF      1e-6f
#define CONF_TH   0.3f

#define FEAT_ITEMS 4096    // 64 frames per item
#define TOT_ITEMS  4160    // + 64 scalar items of 4096 frames

// Output layout (float32, concatenated in reference return order):
// tokens [64*256] | mask [64] | type [64] | conf [64] | s_k [64*8]
#define OUT_TOKENS 0
#define OUT_MASK   16384
#define OUT_TYPE   16448
#define OUT_CONF   16512
#define OUT_SK     16576

// ----- scratch (zero at module load; phase D re-zeros for next replay) -----
__device__ float    g_esum[KSEG * DIN];
__device__ float    g_sumE[KSEG];
__device__ int      g_maxE[KSEG];       // float bits (energy >= 0)
__device__ float    g_sumFC[KSEG];
__device__ float    g_sumSC[KSEG * 3];
__device__ float    g_ent[KSEG];        // sum p*log(p+eps)
__device__ unsigned g_barc = 0;         // barrier arrival counter
__device__ unsigned g_barg = 0;         // barrier generation (monotonic)

// grid-wide barrier: counter + generation (gen monotonic across replays).
__device__ __forceinline__ void gsync(unsigned nblocks) {
    __syncthreads();
    if (threadIdx.x == 0) {
        __threadfence();
        unsigned gen = *(volatile unsigned*)&g_barg;
        if (atomicAdd(&g_barc, 1u) == nblocks - 1u) {
            g_barc = 0;
            __threadfence();
            atomicAdd(&g_barg, 1u);
        } else {
            while (*(volatile unsigned*)&g_barg == gen) __nanosleep(128);
        }
        __threadfence();
    }
    __syncthreads();
}

// segment of frame f = smallest i with send[i] > f (binary search, 6 steps)
__device__ __forceinline__ int seg_of(const int* send, int f) {
    int lo = 0, hi = KSEG - 1;
    #pragma unroll
    for (int it = 0; it < 6; ++it) {
        int mid = (lo + hi) >> 1;
        if (send[mid] > f) hi = mid; else lo = mid + 1;
    }
    return lo;
}

__global__ void __launch_bounds__(256)
k_all(const float4* __restrict__ feat,
      const float*  __restrict__ energy,
      const float*  __restrict__ fconf,
      const float*  __restrict__ sconf,
      const int*    __restrict__ segstart,
      const int*    __restrict__ segend,
      const int*    __restrict__ etype,
      const float*  __restrict__ emb,
      const float*  __restrict__ W,
      const float*  __restrict__ bias,
      const int*    __restrict__ fpsp,
      float*        __restrict__ out) {
    __shared__ int   send[KSEG];
    __shared__ float sinv[KSEG];
    __shared__ float z[ZDIM];

    const int tid = threadIdx.x;
    const unsigned G = gridDim.x;
    if (tid < KSEG) send[tid] = segend[tid];
    __syncthreads();

    // ================= Phase A: accumulate =================
    // items [0,4096): 64-frame feature chunks. Threads [0,128) process the
    //   first 32 frames, [128,256) the last 32; thread col = tid&127 owns
    //   float4 columns [4c,4c+4). Fast path = explicit 8-deep load batches
    //   (all 8 LDG.128 issued before any FADD consumes one -> MLP=8/warp).
    // items [4096,4160): scalar chunks of 4096 frames.
    {
        const int h   = tid >> 7;
        const int col = tid & 127;
        for (int item = blockIdx.x; item < TOT_ITEMS; item += G) {
            if (item < FEAT_ITEMS) {
                const int f0 = item * 64 + h * 32;
                int cur = seg_of(send, f0);
                const float4* p = feat + (size_t)f0 * 128 + col;

                if (send[cur] >= f0 + 32) {
                    // fast path: whole 32-frame half inside one segment
                    float4 a0 = make_float4(0.f, 0.f, 0.f, 0.f);
                    float4 a1 = make_float4(0.f, 0.f, 0.f, 0.f);
                    #pragma unroll 1
                    for (int b = 0; b < 4; ++b) {
                        float4 v[8];
                        #pragma unroll
                        for (int u = 0; u < 8; ++u)
                            v[u] = __ldcs(p + (size_t)(b * 8 + u) * 128);
                        #pragma unroll
                        for (int u = 0; u < 8; u += 2) {
                            a0.x += v[u].x;   a0.y += v[u].y;
                            a0.z += v[u].z;   a0.w += v[u].w;
                            a1.x += v[u+1].x; a1.y += v[u+1].y;
                            a1.z += v[u+1].z; a1.w += v[u+1].w;
                        }
                    }
                    a0.x += a1.x; a0.y += a1.y; a0.z += a1.z; a0.w += a1.w;
                    float* dst = &g_esum[cur * DIN + col * 4];
                    atomicAdd(dst + 0, a0.x); atomicAdd(dst + 1, a0.y);
                    atomicAdd(dst + 2, a0.z); atomicAdd(dst + 3, a0.w);
                } else {
                    // slow path: half straddles a segment boundary
                    float4 acc = make_float4(0.f, 0.f, 0.f, 0.f);
                    const float4* q = p;
                    for (int f = f0; f < f0 + 32; ++f, q += 128) {
                        if (f >= send[cur]) {
                            float* dst = &g_esum[cur * DIN + col * 4];
                            atomicAdd(dst + 0, acc.x); atomicAdd(dst + 1, acc.y);
                            atomicAdd(dst + 2, acc.z); atomicAdd(dst + 3, acc.w);
                            acc = make_float4(0.f, 0.f, 0.f, 0.f);
                            while (send[cur] <= f) cur++;
                        }
                        float4 v = __ldcs(q);
                        acc.x += v.x; acc.y += v.y; acc.z += v.z; acc.w += v.w;
                    }
                    float* dst = &g_esum[cur * DIN + col * 4];
                    atomicAdd(dst + 0, acc.x); atomicAdd(dst + 1, acc.y);
                    atomicAdd(dst + 2, acc.z); atomicAdd(dst + 3, acc.w);
                }
            } else {
                const int base = (item - FEAT_ITEMS) * 4096 + tid;  // 16 iters, stride 256
                int cur = seg_of(send, base);
                float sE = 0.f, mx = 0.f, aF = 0.f, s0 = 0.f, s1 = 0.f, s2 = 0.f;
                #pragma unroll 8
                for (int i = 0; i < 16; ++i) {
                    int f = base + i * 256;
                    if (f >= send[cur]) {
                        atomicAdd(&g_sumE[cur], sE);
                        atomicMax(&g_maxE[cur], __float_as_int(mx));
                        atomicAdd(&g_sumFC[cur], aF);
                        atomicAdd(&g_sumSC[cur * 3 + 0], s0);
                        atomicAdd(&g_sumSC[cur * 3 + 1], s1);
                        atomicAdd(&g_sumSC[cur * 3 + 2], s2);
                        sE = mx = aF = s0 = s1 = s2 = 0.f;
                        while (send[cur] <= f) cur++;
                    }
                    float e = energy[f];
                    sE += e; mx = fmaxf(mx, e);
                    aF += fconf[f];
                    s0 += sconf[3 * f + 0]; s1 += sconf[3 * f + 1]; s2 += sconf[3 * f + 2];
                }
                atomicAdd(&g_sumE[cur], sE);
                atomicMax(&g_maxE[cur], __float_as_int(mx));
                atomicAdd(&g_sumFC[cur], aF);
                atomicAdd(&g_sumSC[cur * 3 + 0], s0);
                atomicAdd(&g_sumSC[cur * 3 + 1], s1);
                atomicAdd(&g_sumSC[cur * 3 + 2], s2);
            }
        }
    }

    gsync(G);

    // ================= Phase B: entropy =================
    if (tid < KSEG) sinv[tid] = 1.f / (g_sumE[tid] + EPSF);
    __syncthreads();

    for (int f = blockIdx.x * 256 + tid; f < TFRAMES; f += G * 256) {
        int cur = seg_of(send, f);
        float p = energy[f] * sinv[cur];
        float v = p * __logf(p + EPSF);
        int first = __shfl_sync(~0u, cur, 0);
        if (__all_sync(~0u, cur == first)) {
            #pragma unroll
            for (int o = 16; o; o >>= 1) v += __shfl_xor_sync(~0u, v, o);
            if ((tid & 31) == 0) atomicAdd(&g_ent[cur], v);
        } else {
            atomicAdd(&g_ent[cur], v);
        }
    }

    gsync(G);

    // ================= Phase C: GEMM + epilogue =================
    const int  iv  = fpsp[0];
    const float fps = (iv >= 1 && iv <= 1000000) ? (float)iv : __int_as_float(iv);

    for (int item = blockIdx.x; item < 257; item += G) {
        if (item < 256) {
            const int k  = item >> 2;
            const int s  = segstart[k];
            const int e  = segend[k];
            const float len = (float)(e - s);
            const float inv = 1.f / len;
            const int  ty   = etype[k];

            float sk[8];
            sk[0] = log1pf(len / fps);
            sk[1] = log1pf((float)s / fps);
            sk[2] = log1pf(g_sumE[k] * inv);
            sk[3] = log1pf(__int_as_float(g_maxE[k]));
            sk[4] = log1pf(-g_ent[k]);
            sk[5] = log1pf(g_sumSC[k * 3 + 0] * inv);
            sk[6] = log1pf(g_sumSC[k * 3 + 1] * inv);
            sk[7] = log1pf(g_sumSC[k * 3 + 2] * inv);

            for (int i = tid; i < ZDIM; i += 256) {
                float v;
                if (i < DIN)            v = g_esum[k * DIN + i] * inv;
                else if (i < DIN + 8)   v = sk[i - DIN];
                else                    v = emb[ty * TYPEEMB + (i - DIN - 8)];
                z[i] = v;
            }
            __syncthreads();

            const int w     = tid >> 5;
            const int lane  = tid & 31;
            const int mbase = (item & 3) * 64 + w * 8;
            #pragma unroll
            for (int r = 0; r < 8; ++r) {
                const int m = mbase + r;
                const float* Wr = W + (size_t)m * ZDIM;
                float acc = 0.f;
                for (int j = lane; j < ZDIM; j += 32) acc += z[j] * Wr[j];
                #pragma unroll
                for (int o = 16; o; o >>= 1) acc += __shfl_xor_sync(~0u, acc, o);
                if (lane == 0) out[OUT_TOKENS + k * DMODEL + m] = acc + bias[m];
            }
            __syncthreads();
        } else if (tid < KSEG) {
            const int k = tid;
            const int s = segstart[k];
            const int e = segend[k];
            const float len = (float)(e - s);
            const float inv = 1.f / len;
            float sk[8];
            sk[0] = log1pf(len / fps);
            sk[1] = log1pf((float)s / fps);
            sk[2] = log1pf(g_sumE[k] * inv);
            sk[3] = log1pf(__int_as_float(g_maxE[k]));
            sk[4] = log1pf(-g_ent[k]);
            sk[5] = log1pf(g_sumSC[k * 3 + 0] * inv);
            sk[6] = log1pf(g_sumSC[k * 3 + 1] * inv);
            sk[7] = log1pf(g_sumSC[k * 3 + 2] * inv);
            #pragma unroll
            for (int i = 0; i < 8; ++i) out[OUT_SK + k * 8 + i] = sk[i];
            float conf = g_sumFC[k] * inv;
            out[OUT_MASK + k] = (conf >= CONF_TH) ? 1.f : 0.f;
            out[OUT_TYPE + k] = (float)etype[k];
            out[OUT_CONF + k] = conf;
        }
    }

    gsync(G);

    // ================= Phase D: re-zero scratch for next replay =============
    for (int i = blockIdx.x * 256 + tid; i < KSEG * DIN; i += G * 256) g_esum[i] = 0.f;
    if (blockIdx.x == 0 && tid < KSEG) {
        g_sumE[tid] = 0.f; g_maxE[tid] = 0; g_sumFC[tid] = 0.f; g_ent[tid] = 0.f;
        g_sumSC[tid * 3 + 0] = 0.f; g_sumSC[tid * 3 + 1] = 0.f; g_sumSC[tid * 3 + 2] = 0.f;
    }
}

// ---------------------------------------------------------------------------
extern "C" void kernel_launch(void* const* d_in, const int* in_sizes, int n_in,
                              void* d_out, int out_size) {
    const float* features  = (const float*)d_in[0];   // [T, 512]
    const float* energy    = (const float*)d_in[1];   // [T]
    const float* fconf     = (const float*)d_in[2];   // [T]
    const float* sconf     = (const float*)d_in[3];   // [T, 3]
    const int*   seg_start = (const int*)  d_in[4];   // [64]
    const int*   seg_end   = (const int*)  d_in[5];   // [64]
    const int*   etype     = (const int*)  d_in[6];   // [64]
    const float* emb       = (const float*)d_in[7];   // [16, 32]
    const float* W         = (const float*)d_in[8];   // [256, 552]
    const float* bias      = (const float*)d_in[9];   // [256]
    const int*   fps       = (const int*)  d_in[10];  // scalar
    float* out = (float*)d_out;

    // persistent grid: exactly the co-resident capacity (barrier safety)
    int sms = 0, occ = 0;
    cudaDeviceGetAttribute(&sms, cudaDevAttrMultiProcessorCount, 0);
    cudaOccupancyMaxActiveBlocksPerMultiprocessor(&occ, k_all, 256, 0);
    if (occ < 1) occ = 1;
    int grid = sms * occ;

    k_all<<<grid, 256>>>((const float4*)features, energy, fconf, sconf,
                         seg_start, seg_end, etype, emb, W, bias, fps, out);
}

// round 8
// speedup vs baseline: 1.3558x; 1.0163x over previous
#include <cuda_runtime.h>
#include <cuda_bf16.h>
#include <cstdint>
#include <cstddef>

// ---------------------------------------------------------------------------
// EventTokenizer, single persistent kernel (1 block/SM) with grid barriers.
// Phase A: features via cp.async.bulk -> smem 6-stage pipeline + scalars
// Phase B: motion entropy   Phase C: GEMM + epilogue   Phase D: re-zero
// ---------------------------------------------------------------------------

#define TFRAMES   262144
#define KSEG      64
#define DIN       512
#define DMODEL    256
#define TYPEEMB   32
#define ZDIM      552      // 512 + 8 + 32
#define EPSF      1e-6f
#define CONF_TH   0.3f

#define CH_FRAMES 16                       // frames per chunk
#define CH_BYTES  (CH_FRAMES * DIN * 4)    // 32768
#define NCHUNK    (TFRAMES / CH_FRAMES)    // 16384
#define NSTAGE    6
#define SMEM_DYN  (NSTAGE * CH_BYTES)      // 196608

// Output layout (float32, concatenated in reference return order):
// tokens [64*256] | mask [64] | type [64] | conf [64] | s_k [64*8]
#define OUT_TOKENS 0
#define OUT_MASK   16384
#define OUT_TYPE   16448
#define OUT_CONF   16512
#define OUT_SK     16576

// ----- scratch (zero at module load; phase D re-zeros for next replay) -----
__device__ float    g_esum[KSEG * DIN];
__device__ float    g_sumE[KSEG];
__device__ int      g_maxE[KSEG];       // float bits (energy >= 0)
__device__ float    g_sumFC[KSEG];
__device__ float    g_sumSC[KSEG * 3];
__device__ float    g_ent[KSEG];
__device__ unsigned g_barc = 0;
__device__ unsigned g_barg = 0;         // monotonic generation

__device__ __forceinline__ void gsync(unsigned nblocks) {
    __syncthreads();
    if (threadIdx.x == 0) {
        __threadfence();
        unsigned gen = *(volatile unsigned*)&g_barg;
        if (atomicAdd(&g_barc, 1u) == nblocks - 1u) {
            g_barc = 0;
            __threadfence();
            atomicAdd(&g_barg, 1u);
        } else {
            while (*(volatile unsigned*)&g_barg == gen) __nanosleep(128);
        }
        __threadfence();
    }
    __syncthreads();
}

__device__ __forceinline__ unsigned s2u(const void* p) {
    return (unsigned)__cvta_generic_to_shared(p);
}

__device__ __forceinline__ void mbar_init(unsigned a, unsigned cnt) {
    asm volatile("mbarrier.init.shared.b64 [%0], %1;" :: "r"(a), "r"(cnt) : "memory");
}
__device__ __forceinline__ void mbar_expect_tx(unsigned a, unsigned bytes) {
    asm volatile("mbarrier.arrive.expect_tx.shared.b64 _, [%0], %1;"
                 :: "r"(a), "r"(bytes) : "memory");
}
__device__ __forceinline__ void bulk_g2s(unsigned dst, const void* src,
                                         unsigned bytes, unsigned mbar) {
    asm volatile("cp.async.bulk.shared::cta.global.mbarrier::complete_tx::bytes "
                 "[%0], [%1], %2, [%3];"
                 :: "r"(dst), "l"(src), "r"(bytes), "r"(mbar) : "memory");
}
__device__ __forceinline__ void mbar_wait(unsigned a, unsigned parity) {
    unsigned done;
    do {
        asm volatile("{\n\t.reg .pred p;\n\t"
                     "mbarrier.try_wait.parity.shared.b64 p, [%1], %2;\n\t"
                     "selp.b32 %0, 1, 0, p;\n\t}"
                     : "=r"(done) : "r"(a), "r"(parity) : "memory");
    } while (!done);
}

// segment of frame f = smallest i with send[i] > f
__device__ __forceinline__ int seg_of(const int* send, int f) {
    int lo = 0, hi = KSEG - 1;
    #pragma unroll
    for (int it = 0; it < 6; ++it) {
        int mid = (lo + hi) >> 1;
        if (send[mid] > f) hi = mid; else lo = mid + 1;
    }
    return lo;
}

__global__ void __launch_bounds__(256)
k_all(const float4* __restrict__ feat,
      const float*  __restrict__ energy,
      const float*  __restrict__ fconf,
      const float*  __restrict__ sconf,
      const int*    __restrict__ segstart,
      const int*    __restrict__ segend,
      const int*    __restrict__ etype,
      const float*  __restrict__ emb,
      const float*  __restrict__ W,
      const float*  __restrict__ bias,
      const int*    __restrict__ fpsp,
      float*        __restrict__ out) {
    extern __shared__ __align__(16) char dsm[];
    __shared__ int   send[KSEG];
    __shared__ float sinv[KSEG];
    __shared__ float z[ZDIM];
    __shared__ alignas(8) unsigned long long mbar[NSTAGE];

    const int tid = threadIdx.x;
    const unsigned G = gridDim.x;
    if (tid < KSEG) send[tid] = segend[tid];
    if (tid == 0) {
        #pragma unroll
        for (int s = 0; s < NSTAGE; ++s) mbar_init(s2u(&mbar[s]), 1u);
    }
    __syncthreads();

    // ================= Phase A: feature pipeline =================
    // Block b owns contiguous chunks [c0,c1); each chunk = 16 frames = 32KB,
    // staged into smem by cp.async.bulk, accumulated from smem.
    {
        const int b  = blockIdx.x;
        const int c0 = (int)(((long long)b * NCHUNK) / G);
        const int c1 = (int)(((long long)(b + 1) * NCHUNK) / G);
        const int n  = c1 - c0;
        const int h   = tid >> 7;      // half: frames [h*8, h*8+8)
        const int col = tid & 127;     // float4 column

        if (tid == 0) {
            const int pre = n < NSTAGE ? n : NSTAGE;
            for (int l = 0; l < pre; ++l) {
                unsigned mb  = s2u(&mbar[l]);
                unsigned dst = s2u(dsm + l * CH_BYTES);
                const char* src = (const char*)feat + (size_t)(c0 + l) * CH_BYTES;
                mbar_expect_tx(mb, CH_BYTES);
                bulk_g2s(dst, src, CH_BYTES, mb);
            }
        }

        float4 acc = make_float4(0.f, 0.f, 0.f, 0.f);
        int cur = seg_of(send, c0 * CH_FRAMES + h * 8);

        #define FLUSH() do { \
            float* d_ = &g_esum[cur * DIN + col * 4]; \
            atomicAdd(d_ + 0, acc.x); atomicAdd(d_ + 1, acc.y); \
            atomicAdd(d_ + 2, acc.z); atomicAdd(d_ + 3, acc.w); \
            acc.x = acc.y = acc.z = acc.w = 0.f; } while (0)

        int st = 0, ph = 0;
        for (int l = 0; l < n; ++l) {
            mbar_wait(s2u(&mbar[st]), (unsigned)ph);
            const int f0 = (c0 + l) * CH_FRAMES;
            const float4* sb = (const float4*)(dsm + st * CH_BYTES);
            const int first = f0 + h * 8;

            if (send[cur] <= first) {           // boundary in the gap
                FLUSH();
                while (send[cur] <= first) cur++;
            }
            if (send[cur] >= first + 8) {
                // fast path: my 8 frames inside one segment
                float4 v[8];
                #pragma unroll
                for (int u = 0; u < 8; ++u) v[u] = sb[(h * 8 + u) * 128 + col];
                #pragma unroll
                for (int u = 0; u < 8; ++u) {
                    acc.x += v[u].x; acc.y += v[u].y;
                    acc.z += v[u].z; acc.w += v[u].w;
                }
            } else {
                for (int f = first; f < first + 8; ++f) {
                    if (f >= send[cur]) {
                        FLUSH();
                        while (send[cur] <= f) cur++;
                    }
                    float4 v = sb[(f - f0) * 128 + col];
                    acc.x += v.x; acc.y += v.y; acc.z += v.z; acc.w += v.w;
                }
            }
            __syncthreads();                    // all readers done with stage st
            if (tid == 0 && l + NSTAGE < n) {
                unsigned mb  = s2u(&mbar[st]);
                unsigned dst = s2u(dsm + st * CH_BYTES);
                const char* src = (const char*)feat + (size_t)(c0 + l + NSTAGE) * CH_BYTES;
                mbar_expect_tx(mb, CH_BYTES);
                bulk_g2s(dst, src, CH_BYTES, mb);
            }
            if (++st == NSTAGE) { st = 0; ph ^= 1; }
        }
        FLUSH();
        #undef FLUSH
    }

    // ---- scalar reductions (6MB): grid-stride over 64 items of 4096 frames
    for (int item = blockIdx.x; item < 64; item += G) {
        const int base = item * 4096 + tid;       // 16 iters, stride 256
        int cur = seg_of(send, base);
        float sE = 0.f, mx = 0.f, aF = 0.f, s0 = 0.f, s1 = 0.f, s2 = 0.f;
        #pragma unroll 8
        for (int i = 0; i < 16; ++i) {
            int f = base + i * 256;
            if (f >= send[cur]) {
                atomicAdd(&g_sumE[cur], sE);
                atomicMax(&g_maxE[cur], __float_as_int(mx));
                atomicAdd(&g_sumFC[cur], aF);
                atomicAdd(&g_sumSC[cur * 3 + 0], s0);
                atomicAdd(&g_sumSC[cur * 3 + 1], s1);
                atomicAdd(&g_sumSC[cur * 3 + 2], s2);
                sE = mx = aF = s0 = s1 = s2 = 0.f;
                while (send[cur] <= f) cur++;
            }
            float e = energy[f];
            sE += e; mx = fmaxf(mx, e);
            aF += fconf[f];
            s0 += sconf[3 * f + 0]; s1 += sconf[3 * f + 1]; s2 += sconf[3 * f + 2];
        }
        atomicAdd(&g_sumE[cur], sE);
        atomicMax(&g_maxE[cur], __float_as_int(mx));
        atomicAdd(&g_sumFC[cur], aF);
        atomicAdd(&g_sumSC[cur * 3 + 0], s0);
        atomicAdd(&g_sumSC[cur * 3 + 1], s1);
        atomicAdd(&g_sumSC[cur * 3 + 2], s2);
    }

    gsync(G);

    // ================= Phase B: entropy =================
    if (tid < KSEG) sinv[tid] = 1.f / (g_sumE[tid] + EPSF);
    __syncthreads();

    for (int f = blockIdx.x * 256 + tid; f < TFRAMES; f += G * 256) {
        int cur = seg_of(send, f);
        float p = energy[f] * sinv[cur];
        float v = p * __logf(p + EPSF);
        int first = __shfl_sync(~0u, cur, 0);
        if (__all_sync(~0u, cur == first)) {
            #pragma unroll
            for (int o = 16; o; o >>= 1) v += __shfl_xor_sync(~0u, v, o);
            if ((tid & 31) == 0) atomicAdd(&g_ent[cur], v);
        } else {
            atomicAdd(&g_ent[cur], v);
        }
    }

    gsync(G);

    // ================= Phase C: GEMM + epilogue =================
    const int  iv  = fpsp[0];
    const float fps = (iv >= 1 && iv <= 1000000) ? (float)iv : __int_as_float(iv);

    for (int item = blockIdx.x; item < 257; item += G) {
        if (item < 256) {
            const int k  = item >> 2;
            const int s  = segstart[k];
            const int e  = segend[k];
            const float len = (float)(e - s);
            const float inv = 1.f / len;
            const int  ty   = etype[k];

            float sk[8];
            sk[0] = log1pf(len / fps);
            sk[1] = log1pf((float)s / fps);
            sk[2] = log1pf(g_sumE[k] * inv);
            sk[3] = log1pf(__int_as_float(g_maxE[k]));
            sk[4] = log1pf(-g_ent[k]);
            sk[5] = log1pf(g_sumSC[k * 3 + 0] * inv);
            sk[6] = log1pf(g_sumSC[k * 3 + 1] * inv);
            sk[7] = log1pf(g_sumSC[k * 3 + 2] * inv);

            for (int i = tid; i < ZDIM; i += 256) {
                float v;
                if (i < DIN)            v = g_esum[k * DIN + i] * inv;
                else if (i < DIN + 8)   v = sk[i - DIN];
                else                    v = emb[ty * TYPEEMB + (i - DIN - 8)];
                z[i] = v;
            }
            __syncthreads();

            const int w     = tid >> 5;
            const int lane  = tid & 31;
            const int mbase = (item & 3) * 64 + w * 8;
            #pragma unroll
            for (int r = 0; r < 8; ++r) {
                const int m = mbase + r;
                const float* Wr = W + (size_t)m * ZDIM;
                float acc = 0.f;
                for (int j = lane; j < ZDIM; j += 32) acc += z[j] * Wr[j];
                #pragma unroll
                for (int o = 16; o; o >>= 1) acc += __shfl_xor_sync(~0u, acc, o);
                if (lane == 0) out[OUT_TOKENS + k * DMODEL + m] = acc + bias[m];
            }
            __syncthreads();
        } else if (tid < KSEG) {
            const int k = tid;
            const int s = segstart[k];
            const int e = segend[k];
            const float len = (float)(e - s);
            const float inv = 1.f / len;
            float sk[8];
            sk[0] = log1pf(len / fps);
            sk[1] = log1pf((float)s / fps);
            sk[2] = log1pf(g_sumE[k] * inv);
            sk[3] = log1pf(__int_as_float(g_maxE[k]));
            sk[4] = log1pf(-g_ent[k]);
            sk[5] = log1pf(g_sumSC[k * 3 + 0] * inv);
            sk[6] = log1pf(g_sumSC[k * 3 + 1] * inv);
            sk[7] = log1pf(g_sumSC[k * 3 + 2] * inv);
            #pragma unroll
            for (int i = 0; i < 8; ++i) out[OUT_SK + k * 8 + i] = sk[i];
            float conf = g_sumFC[k] * inv;
            out[OUT_MASK + k] = (conf >= CONF_TH) ? 1.f : 0.f;
            out[OUT_TYPE + k] = (float)etype[k];
            out[OUT_CONF + k] = conf;
        }
    }

    gsync(G);

    // ================= Phase D: re-zero scratch for next replay =============
    for (int i = blockIdx.x * 256 + tid; i < KSEG * DIN; i += G * 256) g_esum[i] = 0.f;
    if (blockIdx.x == 0 && tid < KSEG) {
        g_sumE[tid] = 0.f; g_maxE[tid] = 0; g_sumFC[tid] = 0.f; g_ent[tid] = 0.f;
        g_sumSC[tid * 3 + 0] = 0.f; g_sumSC[tid * 3 + 1] = 0.f; g_sumSC[tid * 3 + 2] = 0.f;
    }
}

// ---------------------------------------------------------------------------
extern "C" void kernel_launch(void* const* d_in, const int* in_sizes, int n_in,
                              void* d_out, int out_size) {
    const float* features  = (const float*)d_in[0];   // [T, 512]
    const float* energy    = (const float*)d_in[1];   // [T]
    const float* fconf     = (const float*)d_in[2];   // [T]
    const float* sconf     = (const float*)d_in[3];   // [T, 3]
    const int*   seg_start = (const int*)  d_in[4];   // [64]
    const int*   seg_end   = (const int*)  d_in[5];   // [64]
    const int*   etype     = (const int*)  d_in[6];   // [64]
    const float* emb       = (const float*)d_in[7];   // [16, 32]
    const float* W         = (const float*)d_in[8];   // [256, 552]
    const float* bias      = (const float*)d_in[9];   // [256]
    const int*   fps       = (const int*)  d_in[10];  // scalar
    float* out = (float*)d_out;

    cudaFuncSetAttribute(k_all, cudaFuncAttributeMaxDynamicSharedMemorySize, SMEM_DYN);

    int sms = 0, occ = 0;
    cudaDeviceGetAttribute(&sms, cudaDevAttrMultiProcessorCount, 0);
    cudaOccupancyMaxActiveBlocksPerMultiprocessor(&occ, k_all, 256, SMEM_DYN);
    if (occ < 1) occ = 1;
    int grid = sms * occ;

    k_all<<<grid, 256, SMEM_DYN>>>((const float4*)features, energy, fconf, sconf,
                                   seg_start, seg_end, etype, emb, W, bias, fps, out);
}

// round 9
// speedup vs baseline: 1.6091x; 1.1869x over previous
#include <cuda_runtime.h>
#include <cuda_bf16.h>
#include <cstdint>
#include <cstddef>

// ---------------------------------------------------------------------------
// EventTokenizer, single persistent kernel (1 block/SM, 512 threads).
// 144 blocks stream features (cp.async.bulk 6-stage smem pipeline);
// 8 "crew" blocks concurrently do scalars -> entropy -> epilogue.
// Then: gsync -> GEMM -> gsync -> scratch re-zero.
// ---------------------------------------------------------------------------

#define TFRAMES   262144
#define KSEG      64
#define DIN       512
#define DMODEL    256
#define TYPEEMB   32
#define ZDIM      552      // 512 + 8 + 32
#define EPSF      1e-6f
#define CONF_TH   0.3f

#define CH_FRAMES 16
#define CH_BYTES  (CH_FRAMES * DIN * 4)    // 32768
#define NCHUNK    (TFRAMES / CH_FRAMES)    // 16384
#define NSTAGE    6
#define SMEM_DYN  (NSTAGE * CH_BYTES)      // 196608
#define CREW      8
#define NTH       512

// Output layout (float32, reference return order):
// tokens [64*256] | mask [64] | type [64] | conf [64] | s_k [64*8]
#define OUT_TOKENS 0
#define OUT_MASK   16384
#define OUT_TYPE   16448
#define OUT_CONF   16512
#define OUT_SK     16576

// ----- scratch (zero at load; re-zeroed at end for next replay) -----
__device__ float    g_esum[KSEG * DIN];
__device__ float    g_sumE[KSEG];
__device__ int      g_maxE[KSEG];       // float bits (energy >= 0)
__device__ float    g_sumFC[KSEG];
__device__ float    g_sumSC[KSEG * 3];
__device__ float    g_ent[KSEG];
__device__ unsigned g_barc = 0, g_barg = 0;   // full-grid barrier
__device__ unsigned g_cbc = 0, g_cbg = 0;     // crew barrier (8 blocks)

__device__ __forceinline__ void barx(unsigned* cnt, unsigned* gen, unsigned n) {
    __syncthreads();
    if (threadIdx.x == 0) {
        __threadfence();
        unsigned g0 = *(volatile unsigned*)gen;
        if (atomicAdd(cnt, 1u) == n - 1u) {
            *cnt = 0;
            __threadfence();
            atomicAdd(gen, 1u);
        } else {
            while (*(volatile unsigned*)gen == g0) __nanosleep(128);
        }
        __threadfence();
    }
    __syncthreads();
}

__device__ __forceinline__ unsigned s2u(const void* p) {
    return (unsigned)__cvta_generic_to_shared(p);
}
__device__ __forceinline__ void mbar_init(unsigned a, unsigned cnt) {
    asm volatile("mbarrier.init.shared.b64 [%0], %1;" :: "r"(a), "r"(cnt) : "memory");
}
__device__ __forceinline__ void mbar_expect_tx(unsigned a, unsigned bytes) {
    asm volatile("mbarrier.arrive.expect_tx.shared.b64 _, [%0], %1;"
                 :: "r"(a), "r"(bytes) : "memory");
}
__device__ __forceinline__ void bulk_g2s(unsigned dst, const void* src,
                                         unsigned bytes, unsigned mbar) {
    asm volatile("cp.async.bulk.shared::cta.global.mbarrier::complete_tx::bytes "
                 "[%0], [%1], %2, [%3];"
                 :: "r"(dst), "l"(src), "r"(bytes), "r"(mbar) : "memory");
}
__device__ __forceinline__ void mbar_wait(unsigned a, unsigned parity) {
    unsigned done;
    do {
        asm volatile("{\n\t.reg .pred p;\n\t"
                     "mbarrier.try_wait.parity.shared.b64 p, [%1], %2;\n\t"
                     "selp.b32 %0, 1, 0, p;\n\t}"
                     : "=r"(done) : "r"(a), "r"(parity) : "memory");
    } while (!done);
}

// smallest i with send[i] > f
__device__ __forceinline__ int seg_of(const int* send, int f) {
    int lo = 0, hi = KSEG - 1;
    #pragma unroll
    for (int it = 0; it < 6; ++it) {
        int mid = (lo + hi) >> 1;
        if (send[mid] > f) hi = mid; else lo = mid + 1;
    }
    return lo;
}

__global__ void __launch_bounds__(NTH)
k_all(const float4* __restrict__ feat,
      const float*  __restrict__ energy,
      const float*  __restrict__ fconf,
      const float*  __restrict__ sconf,
      const int*    __restrict__ segstart,
      const int*    __restrict__ segend,
      const int*    __restrict__ etype,
      const float*  __restrict__ emb,
      const float*  __restrict__ W,
      const float*  __restrict__ bias,
      const int*    __restrict__ fpsp,
      float*        __restrict__ out) {
    extern __shared__ __align__(16) char dsm[];
    __shared__ int   send[KSEG];
    __shared__ float sinv[KSEG];
    __shared__ float z[ZDIM];
    __shared__ alignas(8) unsigned long long mbar[NSTAGE];

    const int tid = threadIdx.x;
    const unsigned G = gridDim.x;
    const int GF = (int)G - CREW;           // feature-streamer blocks
    if (tid < KSEG) send[tid] = segend[tid];
    if (tid == 0) {
        #pragma unroll
        for (int s = 0; s < NSTAGE; ++s) mbar_init(s2u(&mbar[s]), 1u);
    }
    __syncthreads();

    if ((int)blockIdx.x < GF) {
        // ============ feature streamer: contiguous chunk range ============
        const int b  = blockIdx.x;
        const int c0 = (int)(((long long)b * NCHUNK) / GF);
        const int c1 = (int)(((long long)(b + 1) * NCHUNK) / GF);
        const int n  = c1 - c0;
        const int h   = tid >> 7;      // quarter: frames [h*4, h*4+4)
        const int col = tid & 127;

        if (tid == 0) {
            const int pre = n < NSTAGE ? n : NSTAGE;
            for (int l = 0; l < pre; ++l) {
                mbar_expect_tx(s2u(&mbar[l]), CH_BYTES);
                bulk_g2s(s2u(dsm + l * CH_BYTES),
                         (const char*)feat + (size_t)(c0 + l) * CH_BYTES,
                         CH_BYTES, s2u(&mbar[l]));
            }
        }

        float4 acc = make_float4(0.f, 0.f, 0.f, 0.f);
        int cur = seg_of(send, c0 * CH_FRAMES + h * 4);

        #define FLUSH() do { \
            float* d_ = &g_esum[cur * DIN + col * 4]; \
            atomicAdd(d_ + 0, acc.x); atomicAdd(d_ + 1, acc.y); \
            atomicAdd(d_ + 2, acc.z); atomicAdd(d_ + 3, acc.w); \
            acc.x = acc.y = acc.z = acc.w = 0.f; } while (0)

        int st = 0, ph = 0;
        for (int l = 0; l < n; ++l) {
            mbar_wait(s2u(&mbar[st]), (unsigned)ph);
            const int f0 = (c0 + l) * CH_FRAMES;
            const float4* sb = (const float4*)(dsm + st * CH_BYTES);
            const int first = f0 + h * 4;

            if (send[cur] <= first) {
                FLUSH();
                while (send[cur] <= first) cur++;
            }
            if (send[cur] >= first + 4) {
                float4 v[4];
                #pragma unroll
                for (int u = 0; u < 4; ++u) v[u] = sb[(h * 4 + u) * 128 + col];
                #pragma unroll
                for (int u = 0; u < 4; ++u) {
                    acc.x += v[u].x; acc.y += v[u].y;
                    acc.z += v[u].z; acc.w += v[u].w;
                }
            } else {
                for (int f = first; f < first + 4; ++f) {
                    if (f >= send[cur]) {
                        FLUSH();
                        while (send[cur] <= f) cur++;
                    }
                    float4 v = sb[(f - f0) * 128 + col];
                    acc.x += v.x; acc.y += v.y; acc.z += v.z; acc.w += v.w;
                }
            }
            __syncthreads();
            if (tid == 0 && l + NSTAGE < n) {
                mbar_expect_tx(s2u(&mbar[st]), CH_BYTES);
                bulk_g2s(s2u(dsm + st * CH_BYTES),
                         (const char*)feat + (size_t)(c0 + l + NSTAGE) * CH_BYTES,
                         CH_BYTES, s2u(&mbar[st]));
            }
            if (++st == NSTAGE) { st = 0; ph ^= 1; }
        }
        FLUSH();
        #undef FLUSH
    } else {
        // ============ crew: scalars -> entropy -> epilogue ============
        const int cb   = blockIdx.x - GF;        // 0..7
        const int g    = cb * NTH + tid;         // 0..4095
        const int lane = g & 31;
        const int w0   = (g >> 5) * 2048;        // warp-contiguous 2048 frames

        // ---- scalars (coalesced, per-lane segment walk) ----
        {
            int cur = seg_of(send, w0 + lane);
            float sE = 0.f, mx = 0.f, aF = 0.f, s0 = 0.f, s1 = 0.f, s2 = 0.f;
            #define SFLUSH() do { \
                atomicAdd(&g_sumE[cur], sE); \
                atomicMax(&g_maxE[cur], __float_as_int(mx)); \
                atomicAdd(&g_sumFC[cur], aF); \
                atomicAdd(&g_sumSC[cur * 3 + 0], s0); \
                atomicAdd(&g_sumSC[cur * 3 + 1], s1); \
                atomicAdd(&g_sumSC[cur * 3 + 2], s2); \
                sE = mx = aF = s0 = s1 = s2 = 0.f; } while (0)
            #pragma unroll 8
            for (int i = 0; i < 64; ++i) {
                int f = w0 + i * 32 + lane;
                if (f >= send[cur]) {
                    SFLUSH();
                    while (send[cur] <= f) cur++;
                }
                float e = energy[f];
                sE += e; mx = fmaxf(mx, e);
                aF += fconf[f];
                s0 += sconf[3 * f + 0]; s1 += sconf[3 * f + 1]; s2 += sconf[3 * f + 2];
            }
            SFLUSH();
            #undef SFLUSH
        }

        barx(&g_cbc, &g_cbg, CREW);

        // ---- entropy (needs g_sumE) ----
        if (tid < KSEG) sinv[tid] = 1.f / (g_sumE[tid] + EPSF);
        __syncthreads();
        {
            int cur = seg_of(send, w0 + lane);
            float loc = 0.f;
            #pragma unroll 8
            for (int i = 0; i < 64; ++i) {
                int f = w0 + i * 32 + lane;
                if (f >= send[cur]) {
                    atomicAdd(&g_ent[cur], loc); loc = 0.f;
                    while (send[cur] <= f) cur++;
                }
                float p = energy[f] * sinv[cur];
                loc += p * __logf(p + EPSF);
            }
            atomicAdd(&g_ent[cur], loc);
        }

        barx(&g_cbc, &g_cbg, CREW);

        // ---- epilogue (crew block 0, one thread per segment) ----
        if (cb == 0 && tid < KSEG) {
            const int k = tid;
            const int s = segstart[k];
            const int e = segend[k];
            const float len = (float)(e - s);
            const float inv = 1.f / len;
            const int  iv  = fpsp[0];
            const float fps = (iv >= 1 && iv <= 1000000) ? (float)iv : __int_as_float(iv);
            float sk[8];
            sk[0] = log1pf(len / fps);
            sk[1] = log1pf((float)s / fps);
            sk[2] = log1pf(g_sumE[k] * inv);
            sk[3] = log1pf(__int_as_float(g_maxE[k]));
            sk[4] = log1pf(-g_ent[k]);
            sk[5] = log1pf(g_sumSC[k * 3 + 0] * inv);
            sk[6] = log1pf(g_sumSC[k * 3 + 1] * inv);
            sk[7] = log1pf(g_sumSC[k * 3 + 2] * inv);
            #pragma unroll
            for (int i = 0; i < 8; ++i) out[OUT_SK + k * 8 + i] = sk[i];
            float conf = g_sumFC[k] * inv;
            out[OUT_MASK + k] = (conf >= CONF_TH) ? 1.f : 0.f;
            out[OUT_TYPE + k] = (float)etype[k];
            out[OUT_CONF + k] = conf;
        }
    }

    barx(&g_barc, &g_barg, G);

    // ================= GEMM: tokens[k][m] =================
    {
        const int  iv  = fpsp[0];
        const float fps = (iv >= 1 && iv <= 1000000) ? (float)iv : __int_as_float(iv);

        for (int item = blockIdx.x; item < 256; item += G) {
            const int k  = item >> 2;
            const int s  = segstart[k];
            const int e  = segend[k];
            const float len = (float)(e - s);
            const float inv = 1.f / len;
            const int  ty   = etype[k];

            float sk[8];
            sk[0] = log1pf(len / fps);
            sk[1] = log1pf((float)s / fps);
            sk[2] = log1pf(g_sumE[k] * inv);
            sk[3] = log1pf(__int_as_float(g_maxE[k]));
            sk[4] = log1pf(-g_ent[k]);
            sk[5] = log1pf(g_sumSC[k * 3 + 0] * inv);
            sk[6] = log1pf(g_sumSC[k * 3 + 1] * inv);
            sk[7] = log1pf(g_sumSC[k * 3 + 2] * inv);

            for (int i = tid; i < ZDIM; i += NTH) {
                float v;
                if (i < DIN)            v = g_esum[k * DIN + i] * inv;
                else if (i < DIN + 8)   v = sk[i - DIN];
                else                    v = emb[ty * TYPEEMB + (i - DIN - 8)];
                z[i] = v;
            }
            __syncthreads();

            const int w     = tid >> 5;             // 16 warps
            const int lane  = tid & 31;
            const int mbase = (item & 3) * 64 + w * 4;
            #pragma unroll
            for (int r = 0; r < 4; ++r) {
                const int m = mbase + r;
                const float* Wr = W + (size_t)m * ZDIM;
                float acc = 0.f;
                for (int j = lane; j < ZDIM; j += 32) acc += z[j] * Wr[j];
                #pragma unroll
                for (int o = 16; o; o >>= 1) acc += __shfl_xor_sync(~0u, acc, o);
                if (lane == 0) out[OUT_TOKENS + k * DMODEL + m] = acc + bias[m];
            }
            __syncthreads();
        }
    }

    barx(&g_barc, &g_barg, G);

    // ================= re-zero scratch for next replay =================
    for (int i = blockIdx.x * NTH + tid; i < KSEG * DIN; i += G * NTH) g_esum[i] = 0.f;
    if (blockIdx.x == 0 && tid < KSEG) {
        g_sumE[tid] = 0.f; g_maxE[tid] = 0; g_sumFC[tid] = 0.f; g_ent[tid] = 0.f;
        g_sumSC[tid * 3 + 0] = 0.f; g_sumSC[tid * 3 + 1] = 0.f; g_sumSC[tid * 3 + 2] = 0.f;
    }
}

// ---------------------------------------------------------------------------
extern "C" void kernel_launch(void* const* d_in, const int* in_sizes, int n_in,
                              void* d_out, int out_size) {
    const float* features  = (const float*)d_in[0];   // [T, 512]
    const float* energy    = (const float*)d_in[1];   // [T]
    const float* fconf     = (const float*)d_in[2];   // [T]
    const float* sconf     = (const float*)d_in[3];   // [T, 3]
    const int*   seg_start = (const int*)  d_in[4];   // [64]
    const int*   seg_end   = (const int*)  d_in[5];   // [64]
    const int*   etype     = (const int*)  d_in[6];   // [64]
    const float* emb       = (const float*)d_in[7];   // [16, 32]
    const float* W         = (const float*)d_in[8];   // [256, 552]
    const float* bias      = (const float*)d_in[9];   // [256]
    const int*   fps       = (const int*)  d_in[10];  // scalar
    float* out = (float*)d_out;

    cudaFuncSetAttribute(k_all, cudaFuncAttributeMaxDynamicSharedMemorySize, SMEM_DYN);

    int sms = 0, occ = 0;
    cudaDeviceGetAttribute(&sms, cudaDevAttrMultiProcessorCount, 0);
    cudaOccupancyMaxActiveBlocksPerMultiprocessor(&occ, k_all, NTH, SMEM_DYN);
    if (occ < 1) occ = 1;
    int grid = sms * occ;
    if (grid < CREW + 8) grid = CREW + 8;   // safety floor

    k_all<<<grid, NTH, SMEM_DYN>>>((const float4*)features, energy, fconf, sconf,
                                   seg_start, seg_end, etype, emb, W, bias, fps, out);
}